// round 1
// baseline (speedup 1.0000x reference)
#include <cuda_runtime.h>
#include <cstdint>

#define BB   16
#define C_IN 256
#define CRr  128
#define KKGc 144
#define HWn  3136
#define HH   56
#define WWc  56

// ---------------- scratch (allocation-free: __device__ globals) ----------------
__device__ float g_t[(size_t)BB * CRr * HWn];     // reduce-conv output  [b][cr][hw]
__device__ float g_kern[(size_t)BB * KKGc * HWn]; // span-conv output    [b][o][hw]
__device__ float g_scale[CRr];
__device__ float g_shift[CRr];

// ---------------------------------------------------------------------------
// Tiled fp32 GEMM, per batch z:  C[m][n] = sum_k A[m][k] * Bin[k][n] + bias[m]
// SPAN=true : Bin = relu(g_t * scale + shift), Cout = g_kern   (K=128, M=144)
// SPAN=false: Bin = X (input x),               Cout = g_t      (K=256, M=128)
// Block tile 128x128, BK=16, 256 threads, 8x8 per-thread micro-tile.
// ---------------------------------------------------------------------------
template<int M, int K, bool SPAN>
__global__ __launch_bounds__(256)
void gemm_k(const float* __restrict__ A,
            const float* __restrict__ bias,
            const float* __restrict__ X)
{
    constexpr int BM = 128, BN = 128, BK = 16, TM = 8, TN = 8;
    __shared__ __align__(16) float As[BK][BM + 4];  // +4 pad keeps float4 reads aligned, cuts store conflicts
    __shared__ __align__(16) float Bs[BK][BN];

    const int b   = blockIdx.z;
    const int n0  = blockIdx.x * BN;
    const int m0  = blockIdx.y * BM;
    const int tid = threadIdx.x;
    const int tx  = tid & 15;   // N dim (TN=8)
    const int ty  = tid >> 4;   // M dim (TM=8)

    const float* Bin  = SPAN ? (g_t    + (size_t)b * K * HWn) : (X   + (size_t)b * K * HWn);
    float*       Cout = SPAN ? (g_kern + (size_t)b * M * HWn) : (g_t + (size_t)b * M * HWn);

    float acc[TM][TN] = {};

    // A-tile load mapping: each thread loads 8 contiguous K-floats of one row
    const int arow = tid >> 1;          // 0..127
    const int ak   = (tid & 1) * 8;     // 0 or 8

    for (int k0 = 0; k0 < K; k0 += BK) {
        // ---- load A tile (BMxBK), transposed into As[k][m] ----
        {
            float4 v0, v1;
            const int grow = m0 + arow;
            bool ok = true;
            if constexpr (M % BM != 0) ok = (grow < M);
            if (ok) {
                const float* ap = A + (size_t)grow * K + k0 + ak;
                v0 = *reinterpret_cast<const float4*>(ap);
                v1 = *reinterpret_cast<const float4*>(ap + 4);
            } else {
                v0 = make_float4(0.f, 0.f, 0.f, 0.f); v1 = v0;
            }
            As[ak + 0][arow] = v0.x; As[ak + 1][arow] = v0.y;
            As[ak + 2][arow] = v0.z; As[ak + 3][arow] = v0.w;
            As[ak + 4][arow] = v1.x; As[ak + 5][arow] = v1.y;
            As[ak + 6][arow] = v1.z; As[ak + 7][arow] = v1.w;
        }
        // ---- load B tile (BKxBN), fused BN+ReLU for SPAN ----
        #pragma unroll
        for (int it = 0; it < 2; it++) {
            const int lin  = tid + it * 256;      // 0..511 float4 slots
            const int brow = lin >> 5;            // 0..15
            const int bc4  = lin & 31;            // 0..31
            const int col  = n0 + bc4 * 4;
            float4 v;
            if (col < HWn) {
                v = *reinterpret_cast<const float4*>(Bin + (size_t)(k0 + brow) * HWn + col);
                if constexpr (SPAN) {
                    const int c  = k0 + brow;
                    const float sc = g_scale[c], sh = g_shift[c];
                    v.x = fmaxf(fmaf(v.x, sc, sh), 0.f);
                    v.y = fmaxf(fmaf(v.y, sc, sh), 0.f);
                    v.z = fmaxf(fmaf(v.z, sc, sh), 0.f);
                    v.w = fmaxf(fmaf(v.w, sc, sh), 0.f);
                }
            } else {
                v = make_float4(0.f, 0.f, 0.f, 0.f);
            }
            *reinterpret_cast<float4*>(&Bs[brow][bc4 * 4]) = v;
        }
        __syncthreads();

        // ---- 8x8 micro-tile MACs ----
        #pragma unroll
        for (int k = 0; k < BK; k++) {
            float a[TM], bb[TN];
            float4 a0 = *reinterpret_cast<const float4*>(&As[k][ty * TM]);
            float4 a1 = *reinterpret_cast<const float4*>(&As[k][ty * TM + 4]);
            a[0]=a0.x; a[1]=a0.y; a[2]=a0.z; a[3]=a0.w;
            a[4]=a1.x; a[5]=a1.y; a[6]=a1.z; a[7]=a1.w;
            float4 b0 = *reinterpret_cast<const float4*>(&Bs[k][tx * TN]);
            float4 b1 = *reinterpret_cast<const float4*>(&Bs[k][tx * TN + 4]);
            bb[0]=b0.x; bb[1]=b0.y; bb[2]=b0.z; bb[3]=b0.w;
            bb[4]=b1.x; bb[5]=b1.y; bb[6]=b1.z; bb[7]=b1.w;
            #pragma unroll
            for (int i = 0; i < TM; i++)
                #pragma unroll
                for (int j = 0; j < TN; j++)
                    acc[i][j] = fmaf(a[i], bb[j], acc[i][j]);
        }
        __syncthreads();
    }

    // ---- store (+bias) ----
    const int colb = n0 + tx * TN;     // HWn % 8 == 0, so one guard covers both float4s
    if (colb < HWn) {
        #pragma unroll
        for (int i = 0; i < TM; i++) {
            const int grow = m0 + ty * TM + i;
            bool ok = true;
            if constexpr (M % BM != 0) ok = (grow < M);
            if (ok) {
                const float bv = bias[grow];
                float4 o0, o1;
                o0.x = acc[i][0] + bv; o0.y = acc[i][1] + bv;
                o0.z = acc[i][2] + bv; o0.w = acc[i][3] + bv;
                o1.x = acc[i][4] + bv; o1.y = acc[i][5] + bv;
                o1.z = acc[i][6] + bv; o1.w = acc[i][7] + bv;
                float* cp = Cout + (size_t)grow * HWn + colb;
                *reinterpret_cast<float4*>(cp)     = o0;
                *reinterpret_cast<float4*>(cp + 4) = o1;
            }
        }
    }
}

// ---------------------------------------------------------------------------
// BatchNorm statistics: per CR channel, mean/var over B*H*W (biased), folded
// with gamma/beta into scale/shift. Deterministic fixed-order tree reduction.
// ---------------------------------------------------------------------------
__global__ __launch_bounds__(256)
void bn_stats(const float* __restrict__ gamma, const float* __restrict__ beta)
{
    const int c   = blockIdx.x;
    const int tid = threadIdx.x;
    float s = 0.f, sq = 0.f;
    for (int b = 0; b < BB; b++) {
        const float* p = g_t + ((size_t)b * CRr + c) * HWn;
        for (int i = tid; i < HWn; i += 256) {
            float v = p[i];
            s  += v;
            sq  = fmaf(v, v, sq);
        }
    }
    __shared__ float ss[256], sqs[256];
    ss[tid] = s; sqs[tid] = sq;
    __syncthreads();
    for (int o = 128; o > 0; o >>= 1) {
        if (tid < o) { ss[tid] += ss[tid + o]; sqs[tid] += sqs[tid + o]; }
        __syncthreads();
    }
    if (tid == 0) {
        const float inv  = 1.f / (float)(BB * HWn);
        const float mean = ss[0] * inv;
        const float var  = sqs[0] * inv - mean * mean;
        const float rstd = rsqrtf(var + 1e-5f);
        const float sc   = gamma[c] * rstd;
        g_scale[c] = sc;
        g_shift[c] = beta[c] - mean * sc;
    }
}

// ---------------------------------------------------------------------------
// Involution gather: out[b, g*16+d, h, w] = sum_{i,j} x[b, g*16+d, h+i-1, w+j-1]
//                                               * kern[b, (i*3+j)*16+g, h, w]
// Block = (b, g, h); smem-stage the 9x56 kernel slice shared across all 16 d.
// ---------------------------------------------------------------------------
__global__ __launch_bounds__(448)
void involution_kernel(const float* __restrict__ x, float* __restrict__ out)
{
    const int h = blockIdx.x;
    const int g = blockIdx.y;
    const int b = blockIdx.z;
    const int w  = threadIdx.x;   // 0..55
    const int dy = threadIdx.y;   // 0..7

    __shared__ float sk[9][WWc];
    const int tid = dy * WWc + w;
    const float* kbase = g_kern + ((size_t)b * KKGc + g) * HWn + h * WWc;
    for (int idx = tid; idx < 9 * WWc; idx += 8 * WWc) {
        const int kj = idx / WWc, ww = idx % WWc;
        sk[kj][ww] = kbase[(size_t)kj * 16 * HWn + ww];
    }
    __syncthreads();

    float kv[9];
    #pragma unroll
    for (int t = 0; t < 9; t++) kv[t] = sk[t][w];

    #pragma unroll
    for (int half = 0; half < 2; half++) {
        const int d = dy + half * 8;
        const int c = g * 16 + d;
        const float* xb = x + ((size_t)b * C_IN + c) * HWn;
        float acc = 0.f;
        #pragma unroll
        for (int i = 0; i < 3; i++) {
            const int hh = h + i - 1;
            if (hh < 0 || hh >= HH) continue;
            const float* xr = xb + hh * WWc;
            #pragma unroll
            for (int j = 0; j < 3; j++) {
                const int ww = w + j - 1;
                if (ww >= 0 && ww < WWc)
                    acc = fmaf(xr[ww], kv[i * 3 + j], acc);
            }
        }
        out[((size_t)b * C_IN + c) * HWn + h * WWc + w] = acc;
    }
}

// ---------------------------------------------------------------------------
extern "C" void kernel_launch(void* const* d_in, const int* in_sizes, int n_in,
                              void* d_out, int out_size)
{
    (void)in_sizes; (void)n_in; (void)out_size;
    const float* x        = (const float*)d_in[0];
    const float* w_reduce = (const float*)d_in[1];
    const float* b_reduce = (const float*)d_in[2];
    const float* gamma    = (const float*)d_in[3];
    const float* beta     = (const float*)d_in[4];
    const float* w_span   = (const float*)d_in[5];
    const float* b_span   = (const float*)d_in[6];
    float* out = (float*)d_out;

    // 1) reduce conv:  t = w_reduce @ x + b_reduce          [16] x [128x3136]
    dim3 g1((HWn + 127) / 128, 1, BB);
    gemm_k<CRr, C_IN, false><<<g1, 256>>>(w_reduce, b_reduce, x);

    // 2) BN batch statistics -> folded scale/shift
    bn_stats<<<CRr, 256>>>(gamma, beta);

    // 3) span conv with fused BN+ReLU on input: kern = w_span @ relu(bn(t)) + b_span
    dim3 g2((HWn + 127) / 128, (KKGc + 127) / 128, BB);
    gemm_k<KKGc, CRr, true><<<g2, 256>>>(w_span, b_span, nullptr);

    // 4) involution gather
    dim3 g3(HH, 16, BB);
    involution_kernel<<<g3, dim3(WWc, 8)>>>(x, out);
}

// round 2
// speedup vs baseline: 1.2310x; 1.2310x over previous
#include <cuda_runtime.h>
#include <cstdint>

#define BB   16
#define C_IN 256
#define CRr  128
#define KKGc 144
#define HWn  3136
#define HH   56
#define WWc  56

// ---------------- scratch (allocation-free: __device__ globals) ----------------
__device__ float g_t[(size_t)BB * CRr * HWn];     // reduce-conv output  [b][cr][hw]
__device__ float g_kern[(size_t)BB * KKGc * HWn]; // span-conv output    [b][o][hw]
__device__ float g_scale[CRr];
__device__ float g_shift[CRr];

// ---------------- packed fp32x2 helpers (Blackwell f32x2 pipe) ----------------
__device__ __forceinline__ unsigned long long dup2(float x) {
    unsigned long long r;
    asm("mov.b64 %0, {%1, %1};" : "=l"(r) : "f"(x));
    return r;
}
__device__ __forceinline__ void fma2(unsigned long long& acc,
                                     unsigned long long a,
                                     unsigned long long b) {
    asm("fma.rn.f32x2 %0, %1, %2, %0;" : "+l"(acc) : "l"(a), "l"(b));
}
__device__ __forceinline__ void unpack2(unsigned long long v, float& lo, float& hi) {
    asm("mov.b64 {%0, %1}, %2;" : "=f"(lo), "=f"(hi) : "l"(v));
}

// ---------------------------------------------------------------------------
// Tiled fp32 GEMM (f32x2-packed), per batch z:
//   C[m][n] = sum_k A[m][k] * Bin[k][n] + bias[m]
// SPAN=true : Bin = relu(g_t * scale + shift), Cout = g_kern   (K=128, M=144)
// SPAN=false: Bin = X (input x),               Cout = g_t      (K=256, M=128)
// Block tile 128x128, BK=16, 256 threads, 8x8 micro-tile as 8x4 packed pairs.
// ---------------------------------------------------------------------------
template<int M, int K, bool SPAN>
__global__ __launch_bounds__(256)
void gemm_k(const float* __restrict__ A,
            const float* __restrict__ bias,
            const float* __restrict__ X)
{
    constexpr int BM = 128, BN = 128, BK = 16, TM = 8, TN = 8;
    __shared__ __align__(16) float As[BK][BM + 4];
    __shared__ __align__(16) float Bs[BK][BN];

    const int b   = blockIdx.z;
    const int n0  = blockIdx.x * BN;
    const int m0  = blockIdx.y * BM;
    const int tid = threadIdx.x;
    const int tx  = tid & 15;   // N dim
    const int ty  = tid >> 4;   // M dim

    const float* Bin  = SPAN ? (g_t    + (size_t)b * K * HWn) : (X   + (size_t)b * K * HWn);
    float*       Cout = SPAN ? (g_kern + (size_t)b * M * HWn) : (g_t + (size_t)b * M * HWn);

    // warp-aligned skip for the partial M block (M=144: block y=1 has only 16 live rows)
    bool active = true;
    if constexpr (M % BM != 0) active = (m0 + ty * TM) < M;

    unsigned long long acc2[TM][TN / 2] = {};   // packed {lo,hi} fp32 pairs

    const int arow = tid >> 1;
    const int ak   = (tid & 1) * 8;

    for (int k0 = 0; k0 < K; k0 += BK) {
        // ---- load A tile (BMxBK), transposed into As[k][m] ----
        {
            float4 v0, v1;
            const int grow = m0 + arow;
            bool ok = true;
            if constexpr (M % BM != 0) ok = (grow < M);
            if (ok) {
                const float* ap = A + (size_t)grow * K + k0 + ak;
                v0 = *reinterpret_cast<const float4*>(ap);
                v1 = *reinterpret_cast<const float4*>(ap + 4);
            } else {
                v0 = make_float4(0.f, 0.f, 0.f, 0.f); v1 = v0;
            }
            As[ak + 0][arow] = v0.x; As[ak + 1][arow] = v0.y;
            As[ak + 2][arow] = v0.z; As[ak + 3][arow] = v0.w;
            As[ak + 4][arow] = v1.x; As[ak + 5][arow] = v1.y;
            As[ak + 6][arow] = v1.z; As[ak + 7][arow] = v1.w;
        }
        // ---- load B tile (BKxBN), fused BN+ReLU for SPAN ----
        #pragma unroll
        for (int it = 0; it < 2; it++) {
            const int lin  = tid + it * 256;
            const int brow = lin >> 5;
            const int bc4  = lin & 31;
            const int col  = n0 + bc4 * 4;
            float4 v;
            if (col < HWn) {
                v = *reinterpret_cast<const float4*>(Bin + (size_t)(k0 + brow) * HWn + col);
                if constexpr (SPAN) {
                    const int c  = k0 + brow;
                    const float sc = g_scale[c], sh = g_shift[c];
                    v.x = fmaxf(fmaf(v.x, sc, sh), 0.f);
                    v.y = fmaxf(fmaf(v.y, sc, sh), 0.f);
                    v.z = fmaxf(fmaf(v.z, sc, sh), 0.f);
                    v.w = fmaxf(fmaf(v.w, sc, sh), 0.f);
                }
            } else {
                v = make_float4(0.f, 0.f, 0.f, 0.f);
            }
            *reinterpret_cast<float4*>(&Bs[brow][bc4 * 4]) = v;
        }
        __syncthreads();

        if (active) {
            #pragma unroll
            for (int k = 0; k < BK; k++) {
                float4 a0 = *reinterpret_cast<const float4*>(&As[k][ty * TM]);
                float4 a1 = *reinterpret_cast<const float4*>(&As[k][ty * TM + 4]);
                unsigned long long ad[TM];
                ad[0] = dup2(a0.x); ad[1] = dup2(a0.y);
                ad[2] = dup2(a0.z); ad[3] = dup2(a0.w);
                ad[4] = dup2(a1.x); ad[5] = dup2(a1.y);
                ad[6] = dup2(a1.z); ad[7] = dup2(a1.w);
                const unsigned long long* bp =
                    reinterpret_cast<const unsigned long long*>(&Bs[k][tx * TN]);
                unsigned long long b2[4];
                b2[0] = bp[0]; b2[1] = bp[1]; b2[2] = bp[2]; b2[3] = bp[3];
                #pragma unroll
                for (int i = 0; i < TM; i++)
                    #pragma unroll
                    for (int j = 0; j < TN / 2; j++)
                        fma2(acc2[i][j], ad[i], b2[j]);
            }
        }
        __syncthreads();
    }

    // ---- store (+bias) ----
    const int colb = n0 + tx * TN;
    if (active && colb < HWn) {
        #pragma unroll
        for (int i = 0; i < TM; i++) {
            const int grow = m0 + ty * TM + i;
            bool ok = true;
            if constexpr (M % BM != 0) ok = (grow < M);
            if (ok) {
                const float bv = bias[grow];
                float o[TN];
                #pragma unroll
                for (int j = 0; j < TN / 2; j++)
                    unpack2(acc2[i][j], o[2 * j], o[2 * j + 1]);
                float4 o0, o1;
                o0.x = o[0] + bv; o0.y = o[1] + bv; o0.z = o[2] + bv; o0.w = o[3] + bv;
                o1.x = o[4] + bv; o1.y = o[5] + bv; o1.z = o[6] + bv; o1.w = o[7] + bv;
                float* cp = Cout + (size_t)grow * HWn + colb;
                *reinterpret_cast<float4*>(cp)     = o0;
                *reinterpret_cast<float4*>(cp + 4) = o1;
            }
        }
    }
}

// ---------------------------------------------------------------------------
// BatchNorm statistics: per CR channel, mean/var over B*H*W (biased), folded
// with gamma/beta into scale/shift. Deterministic fixed-order tree reduction.
// ---------------------------------------------------------------------------
__global__ __launch_bounds__(1024)
void bn_stats(const float* __restrict__ gamma, const float* __restrict__ beta)
{
    const int c   = blockIdx.x;
    const int tid = threadIdx.x;
    float s = 0.f, sq = 0.f;
    for (int b = 0; b < BB; b++) {
        const float* p = g_t + ((size_t)b * CRr + c) * HWn;
        for (int i = tid; i < HWn; i += 1024) {
            float v = p[i];
            s  += v;
            sq  = fmaf(v, v, sq);
        }
    }
    __shared__ float ss[1024], sqs[1024];
    ss[tid] = s; sqs[tid] = sq;
    __syncthreads();
    for (int o = 512; o > 0; o >>= 1) {
        if (tid < o) { ss[tid] += ss[tid + o]; sqs[tid] += sqs[tid + o]; }
        __syncthreads();
    }
    if (tid == 0) {
        const float inv  = 1.f / (float)(BB * HWn);
        const float mean = ss[0] * inv;
        const float var  = sqs[0] * inv - mean * mean;
        const float rstd = rsqrtf(var + 1e-5f);
        const float sc   = gamma[c] * rstd;
        g_scale[c] = sc;
        g_shift[c] = beta[c] - mean * sc;
    }
}

// ---------------------------------------------------------------------------
// Involution gather, h-tiled + smem-staged, bounds-check-free inner loop.
// Block = (h_tile, g, b), 224 threads. Each thread owns (w, h_local), keeps its
// 9 kernel taps in registers, loops over the 16 d-channels of the group.
//   out[b, g*16+d, h, w] = sum_{i,j} x[b, g*16+d, h+i-1, w+j-1]
//                              * kern[b, (i*3+j)*16+g, h, w]
// ---------------------------------------------------------------------------
#define THT 4
__global__ __launch_bounds__(224)
void involution_kernel(const float* __restrict__ x, float* __restrict__ out)
{
    __shared__ float sx[16][THT + 2][60];   // x tile with halo, padded rows
    __shared__ float skn[9][THT][WWc];      // 9 taps for THT output rows

    const int h0  = blockIdx.x * THT;
    const int g   = blockIdx.y;
    const int b   = blockIdx.z;
    const int tid = threadIdx.x;            // 0..223

    // ---- stage x tile: 16 d x (THT+2) rows x 58 cols (halo zero-filled) ----
    const float* xg = x + ((size_t)b * C_IN + g * 16) * HWn;
    for (int idx = tid; idx < 16 * (THT + 2) * 58; idx += 224) {
        const int d    = idx / ((THT + 2) * 58);
        const int r    = (idx / 58) % (THT + 2);
        const int cpos = idx % 58;
        const int hh   = h0 - 1 + r;
        const int ww   = cpos - 1;
        float v = 0.f;
        if (hh >= 0 && hh < HH && ww >= 0 && ww < WWc)
            v = xg[(size_t)d * HWn + hh * WWc + ww];
        sx[d][r][cpos] = v;
    }
    // ---- stage kernel slice: 9 taps x THT rows x 56 ----
    const float* kg = g_kern + ((size_t)b * KKGc + g) * HWn + h0 * WWc;
    for (int idx = tid; idx < 9 * THT * WWc; idx += 224) {
        const int t  = idx / (THT * WWc);
        const int r  = (idx / WWc) % THT;
        const int ww = idx % WWc;
        skn[t][r][ww] = kg[(size_t)t * 16 * HWn + r * WWc + ww];
    }
    __syncthreads();

    const int w  = tid % WWc;
    const int hl = tid / WWc;   // 0..3

    float kv[9];
    #pragma unroll
    for (int t = 0; t < 9; t++) kv[t] = skn[t][hl][w];

    float* og = out + ((size_t)b * C_IN + g * 16) * HWn + (h0 + hl) * WWc + w;
    #pragma unroll 4
    for (int d = 0; d < 16; d++) {
        float acc = 0.f;
        #pragma unroll
        for (int i = 0; i < 3; i++)
            #pragma unroll
            for (int j = 0; j < 3; j++)
                acc = fmaf(sx[d][hl + i][w + j], kv[i * 3 + j], acc);
        og[(size_t)d * HWn] = acc;
    }
}

// ---------------------------------------------------------------------------
extern "C" void kernel_launch(void* const* d_in, const int* in_sizes, int n_in,
                              void* d_out, int out_size)
{
    (void)in_sizes; (void)n_in; (void)out_size;
    const float* x        = (const float*)d_in[0];
    const float* w_reduce = (const float*)d_in[1];
    const float* b_reduce = (const float*)d_in[2];
    const float* gamma    = (const float*)d_in[3];
    const float* beta     = (const float*)d_in[4];
    const float* w_span   = (const float*)d_in[5];
    const float* b_span   = (const float*)d_in[6];
    float* out = (float*)d_out;

    // 1) reduce conv:  t = w_reduce @ x + b_reduce
    dim3 g1((HWn + 127) / 128, 1, BB);
    gemm_k<CRr, C_IN, false><<<g1, 256>>>(w_reduce, b_reduce, x);

    // 2) BN batch statistics -> folded scale/shift
    bn_stats<<<CRr, 1024>>>(gamma, beta);

    // 3) span conv with fused BN+ReLU: kern = w_span @ relu(bn(t)) + b_span
    dim3 g2((HWn + 127) / 128, (KKGc + 127) / 128, BB);
    gemm_k<KKGc, CRr, true><<<g2, 256>>>(w_span, b_span, nullptr);

    // 4) involution gather
    dim3 g3(HH / THT, 16, BB);
    involution_kernel<<<g3, 224>>>(x, out);
}